// round 7
// baseline (speedup 1.0000x reference)
#include <cuda_runtime.h>

#define BATCH  32
#define NP     4096
#define NSLOT  64                    // (cloud w, batch b)
#define GD     40
#define NCELLS (GD * GD * GD)        // 64000
#define GMIN   (-7.5f)
#define H      0.375f
#define INVH   2.6666666667f
#define SC     (GD / 2)              // 20 supercells per dim
#define NSC    (SC * SC * SC)        // 8000
#define MAXWL  98304
#define QTHREADS 128
#define CAP    2048                  // candidate smem capacity (32 KB)

__device__ int            g_cnt[NSLOT][NCELLS];
__device__ unsigned       g_cs [NSLOT][NCELLS];   // (start<<16)|count
__device__ int            g_cur[NSLOT][NCELLS];
__device__ float4         g_pts[NSLOT][NP];       // (-2x,-2y,-2z,||c||^2), binned
__device__ unsigned short g_qid[NSLOT][NP];
__device__ float          g_dist[NSLOT][NP];      // by ORIGINAL index
__device__ int            g_wl_cnt;
__device__ unsigned       g_wl[MAXWL];            // (slot<<13)|supercell

static __device__ __forceinline__ int cell_coord(float v) {
    int c = (int)floorf((v - GMIN) * INVH);
    return min(max(c, 0), GD - 1);
}

// 1) zero counts + worklist counter
__global__ void zero_kernel() {
    int4* p = (int4*)g_cnt;
    int n = NSLOT * NCELLS / 4;
    int i = blockIdx.x * blockDim.x + threadIdx.x;
    if (i < n) p[i] = make_int4(0, 0, 0, 0);
    if (i == 0) g_wl_cnt = 0;
}

// 2) histogram
__global__ void count_kernel(const float* __restrict__ x1,
                             const float* __restrict__ x2) {
    int gid = blockIdx.x * blockDim.x + threadIdx.x;
    if (gid >= NSLOT * NP) return;
    int s = gid / NP, p = gid - s * NP;
    int w = s / BATCH, b = s - w * BATCH;
    const float* src = (w ? x2 : x1) + ((size_t)b * NP + p) * 3;
    int cx = cell_coord(src[0]), cy = cell_coord(src[1]), cz = cell_coord(src[2]);
    atomicAdd(&g_cnt[s][(cz * GD + cy) * GD + cx], 1);
}

// 3) per-slot exclusive scan (512 threads x 125 cells = 64000)
__global__ void __launch_bounds__(512)
scan_kernel() {
    const int s = blockIdx.x, tid = threadIdx.x;
    const int per = NCELLS / 512;
    const int base = tid * per;

    int lsum = 0;
    for (int i = 0; i < per; i++) lsum += g_cnt[s][base + i];

    __shared__ int wsum[16];
    int lane = tid & 31, wid = tid >> 5;
    int v = lsum;
    #pragma unroll
    for (int o = 1; o < 32; o <<= 1) {
        int n = __shfl_up_sync(0xffffffffu, v, o);
        if (lane >= o) v += n;
    }
    if (lane == 31) wsum[wid] = v;
    __syncthreads();
    if (wid == 0) {
        int t = (lane < 16) ? wsum[lane] : 0;
        #pragma unroll
        for (int o = 1; o < 16; o <<= 1) {
            int n = __shfl_up_sync(0xffffffffu, t, o);
            if (lane >= o) t += n;
        }
        if (lane < 16) wsum[lane] = t;
    }
    __syncthreads();
    int offset = (v - lsum) + (wid > 0 ? wsum[wid - 1] : 0);

    int run = offset;
    for (int i = 0; i < per; i++) {
        int c = g_cnt[s][base + i];
        g_cs[s][base + i] = ((unsigned)run << 16) | (unsigned)c;
        g_cur[s][base + i] = run;
        run += c;
    }
}

// 4) scatter into binned order
__global__ void scatter_kernel(const float* __restrict__ x1,
                               const float* __restrict__ x2) {
    int gid = blockIdx.x * blockDim.x + threadIdx.x;
    if (gid >= NSLOT * NP) return;
    int s = gid / NP, p = gid - s * NP;
    int w = s / BATCH, b = s - w * BATCH;
    const float* src = (w ? x2 : x1) + ((size_t)b * NP + p) * 3;
    float x = src[0], y = src[1], z = src[2];
    int cx = cell_coord(x), cy = cell_coord(y), cz = cell_coord(z);
    int pos = atomicAdd(&g_cur[s][(cz * GD + cy) * GD + cx], 1);
    g_pts[s][pos] = make_float4(-2.0f * x, -2.0f * y, -2.0f * z,
                                x * x + y * y + z * z);
    g_qid[s][pos] = (unsigned short)p;
}

// 5) build worklist of occupied supercells
__global__ void wl_kernel() {
    int gid = blockIdx.x * blockDim.x + threadIdx.x;
    if (gid >= NSLOT * NSC) return;
    int s = gid / NSC, sc = gid - s * NSC;
    int scz = sc / (SC * SC);
    int rem = sc - scz * SC * SC;
    int scy = rem / SC, scx = rem - scy * SC;
    int X0 = 2 * scx, Y0 = 2 * scy, Z0 = 2 * scz;
    int sum = 0;
    #pragma unroll
    for (int dz = 0; dz < 2; dz++)
        #pragma unroll
        for (int dy = 0; dy < 2; dy++)
            #pragma unroll
            for (int dx = 0; dx < 2; dx++)
                sum += g_cnt[s][((Z0 + dz) * GD + Y0 + dy) * GD + X0 + dx];
    if (sum > 0) {
        int pos = atomicAdd(&g_wl_cnt, 1);
        if (pos < MAXWL) g_wl[pos] = ((unsigned)s << 13) | (unsigned)sc;
    }
}

// exact per-thread expanding-box fallback (rare: sparse-tail queries)
static __device__ float fb_search(const unsigned* __restrict__ cs,
                                  const float4* __restrict__ pts,
                                  float qx, float qy, float qz, float qq,
                                  float m, int cx, int cy, int cz) {
    const float INF = __int_as_float(0x7f800000);
    for (int r = 2;; r++) {
        int zlo = max(cz - r, 0), zhi = min(cz + r, GD - 1);
        int ylo = max(cy - r, 0), yhi = min(cy + r, GD - 1);
        int xlo = max(cx - r, 0), xhi = min(cx + r, GD - 1);
        for (int z = zlo; z <= zhi; z++)
            for (int y = ylo; y <= yhi; y++) {
                int rowbase = (z * GD + y) * GD;
                unsigned e0 = cs[rowbase + xlo];
                unsigned e1 = cs[rowbase + xhi];
                int s0 = (int)(e0 >> 16);
                int e  = (int)((e1 >> 16) + (e1 & 0xffffu));
                for (int i = s0; i < e; i++) {
                    float4 c = pts[i];
                    m = fminf(m, fmaf(qx, c.x,
                                 fmaf(qy, c.y, fmaf(qz, c.z, c.w))));
                }
            }
        float bnd = INF;
        if (cx - r > 0)      bnd = fminf(bnd, qx - (GMIN + (float)(cx - r) * H));
        if (cx + r < GD - 1) bnd = fminf(bnd, (GMIN + (float)(cx + r + 1) * H) - qx);
        if (cy - r > 0)      bnd = fminf(bnd, qy - (GMIN + (float)(cy - r) * H));
        if (cy + r < GD - 1) bnd = fminf(bnd, (GMIN + (float)(cy + r + 1) * H) - qy);
        if (cz - r > 0)      bnd = fminf(bnd, qz - (GMIN + (float)(cz - r) * H));
        if (cz + r < GD - 1) bnd = fminf(bnd, (GMIN + (float)(cz + r + 1) * H) - qz);
        float bd = qq + m;
        if (bd <= bnd * bnd || r >= GD) return m;
    }
}

// 6) supercell query kernel: block = one occupied supercell.
//    Load 4x4x4-cell candidate box to SMEM (16 contiguous row ranges),
//    then each thread = one query scanning the shared list (broadcast LDS).
__global__ void __launch_bounds__(QTHREADS)
query_kernel() {
    __shared__ int qs[8], qc[8], qpre[9];
    __shared__ int crs[16], cln[16], cpre[17];
    __shared__ float4 scand[CAP];

    int bid = blockIdx.x;
    if (bid >= g_wl_cnt) return;
    unsigned ent = g_wl[bid];
    int sq = (int)(ent >> 13);
    int scid = (int)(ent & 8191u);
    int scz = scid / (SC * SC);
    int rem = scid - scz * SC * SC;
    int scy = rem / SC, scx = rem - scy * SC;
    int X0 = 2 * scx, Y0 = 2 * scy, Z0 = 2 * scz;
    int sc = sq ^ BATCH;                       // opposite cloud, same batch

    const unsigned* __restrict__ csq  = g_cs[sq];
    const unsigned* __restrict__ csc  = g_cs[sc];
    const float4*   __restrict__ ptsq = g_pts[sq];
    const float4*   __restrict__ ptsc = g_pts[sc];

    int tid = threadIdx.x;
    if (tid < 8) {
        int dx = tid & 1, dy = (tid >> 1) & 1, dz = tid >> 2;
        unsigned d = csq[((Z0 + dz) * GD + Y0 + dy) * GD + X0 + dx];
        qs[tid] = (int)(d >> 16);
        qc[tid] = (int)(d & 0xffffu);
    } else if (tid < 24) {
        int r = tid - 8;
        int z = Z0 - 1 + (r >> 2);
        int y = Y0 - 1 + (r & 3);
        int st = 0, len = 0;
        if (z >= 0 && z < GD && y >= 0 && y < GD) {
            int xlo = max(X0 - 1, 0), xhi = min(X0 + 2, GD - 1);
            int rowbase = (z * GD + y) * GD;
            unsigned e0 = csc[rowbase + xlo];
            unsigned e1 = csc[rowbase + xhi];
            st  = (int)(e0 >> 16);
            len = (int)((e1 >> 16) + (e1 & 0xffffu)) - st;
        }
        crs[r] = st;
        cln[r] = len;
    }
    __syncthreads();
    if (tid == 0) {
        int a = 0;
        for (int i = 0; i < 8; i++) { qpre[i] = a; a += qc[i]; }
        qpre[8] = a;
        a = 0;
        for (int i = 0; i < 16; i++) { cpre[i] = a; a += cln[i]; }
        cpre[16] = a;
    }
    __syncthreads();
    const int nq = qpre[8], ncand = cpre[16];
    const float INF = __int_as_float(0x7f800000);

    for (int qb = 0; qb < nq; qb += QTHREADS) {
        int t = qb + tid;
        bool active = t < nq;
        float qx = 0.f, qy = 0.f, qz = 0.f, qq = 0.f;
        int qid = 0;
        if (active) {
            int c = 0;
            while (t >= qpre[c + 1]) c++;
            int qidx = qs[c] + (t - qpre[c]);
            float4 qp = ptsq[qidx];
            qid = g_qid[sq][qidx];
            qx = -0.5f * qp.x;        // exact: bitwise inverse of -2x
            qy = -0.5f * qp.y;
            qz = -0.5f * qp.z;
            qq = qp.w;
        }
        float m0 = INF, m1 = INF, m2 = INF, m3 = INF;

        for (int cb = 0; cb < ncand; cb += CAP) {
            int nw = min(CAP, ncand - cb);
            __syncthreads();
            for (int r = 0; r < 16; r++) {
                int p0 = cpre[r], L = cln[r];
                int j0 = max(cb - p0, 0);
                int j1 = min(cb + CAP - p0, L);
                for (int j = j0 + tid; j < j1; j += QTHREADS)
                    scand[p0 + j - cb] = ptsc[crs[r] + j];
            }
            __syncthreads();
            if (active) {
                int j = 0;
                for (; j + 3 < nw; j += 4) {
                    float4 a = scand[j];
                    float4 b = scand[j + 1];
                    float4 c = scand[j + 2];
                    float4 d = scand[j + 3];
                    m0 = fminf(m0, fmaf(qx, a.x, fmaf(qy, a.y, fmaf(qz, a.z, a.w))));
                    m1 = fminf(m1, fmaf(qx, b.x, fmaf(qy, b.y, fmaf(qz, b.z, b.w))));
                    m2 = fminf(m2, fmaf(qx, c.x, fmaf(qy, c.y, fmaf(qz, c.z, c.w))));
                    m3 = fminf(m3, fmaf(qx, d.x, fmaf(qy, d.y, fmaf(qz, d.z, d.w))));
                }
                for (; j < nw; j++) {
                    float4 a = scand[j];
                    m0 = fminf(m0, fmaf(qx, a.x, fmaf(qy, a.y, fmaf(qz, a.z, a.w))));
                }
            }
        }

        if (active) {
            float m = fminf(fminf(m0, m1), fminf(m2, m3));
            // exact uncovered-face bound of the 4x4x4 box [X0-1, X0+2] etc.
            float bnd = INF;
            if (X0 - 1 > 0)      bnd = fminf(bnd, qx - (GMIN + (float)(X0 - 1) * H));
            if (X0 + 2 < GD - 1) bnd = fminf(bnd, (GMIN + (float)(X0 + 3) * H) - qx);
            if (Y0 - 1 > 0)      bnd = fminf(bnd, qy - (GMIN + (float)(Y0 - 1) * H));
            if (Y0 + 2 < GD - 1) bnd = fminf(bnd, (GMIN + (float)(Y0 + 3) * H) - qy);
            if (Z0 - 1 > 0)      bnd = fminf(bnd, qz - (GMIN + (float)(Z0 - 1) * H));
            if (Z0 + 2 < GD - 1) bnd = fminf(bnd, (GMIN + (float)(Z0 + 3) * H) - qz);
            float bd = qq + m;
            if (!(bd <= bnd * bnd)) {
                int cx = cell_coord(qx), cy = cell_coord(qy), cz = cell_coord(qz);
                m = fb_search(csc, ptsc, qx, qy, qz, qq, m, cx, cy, cz);
                bd = qq + m;
            }
            g_dist[sq][qid] = bd;
        }
    }
}

// 7) deterministic fixed-order reduce
__global__ void __launch_bounds__(256)
reduce_kernel(float* __restrict__ out) {
    const int b = blockIdx.x, tid = threadIdx.x;
    float s = 0.0f;
    #pragma unroll
    for (int d = 0; d < 2; d++)
        for (int i = tid; i < NP; i += 256)
            s += g_dist[d * BATCH + b][i];

    __shared__ float red[256];
    red[tid] = s;
    __syncthreads();
    #pragma unroll
    for (int o = 128; o > 0; o >>= 1) {
        if (tid < o) red[tid] += red[tid + o];
        __syncthreads();
    }
    if (tid == 0) out[b] = red[0] * (1.0f / (float)NP);
}

extern "C" void kernel_launch(void* const* d_in, const int* in_sizes, int n_in,
                              void* d_out, int out_size) {
    const float* x1 = (const float*)d_in[0];
    const float* x2 = (const float*)d_in[1];
    float* out = (float*)d_out;

    int zn = NSLOT * NCELLS / 4;
    zero_kernel<<<(zn + 255) / 256, 256>>>();
    int pn = NSLOT * NP;
    count_kernel<<<(pn + 255) / 256, 256>>>(x1, x2);
    scan_kernel<<<NSLOT, 512>>>();
    scatter_kernel<<<(pn + 255) / 256, 256>>>(x1, x2);
    int wn = NSLOT * NSC;
    wl_kernel<<<(wn + 255) / 256, 256>>>();
    query_kernel<<<MAXWL, QTHREADS>>>();
    reduce_kernel<<<BATCH, 256>>>(out);
}

// round 8
// speedup vs baseline: 1.1747x; 1.1747x over previous
#include <cuda_runtime.h>

#define BATCH  32
#define NP     4096
#define NSLOT  64                 // slot = w*32 + b; opposite slot = s ^ 32
#define NCHUNK 8                  // query chunks per slot
#define QCH    (NP / NCHUNK)      // 512 queries per chunk
#define WIN    2048               // candidate smem window (32 KB)
#define EPS    1e-5f

// points sorted ascending by x, preprocessed: (-2x, -2y, -2z, ||c||^2)
__device__ float4         g_pts[NSLOT][NP];
__device__ unsigned short g_qid[NSLOT][NP];   // original index of sorted point
__device__ float          g_dist[NSLOT][NP];  // per-query dist, by ORIGINAL index

// ---------------------------------------------------------------------------
// 1) per-slot bitonic sort by x + preprocess.  One block per slot.
// ---------------------------------------------------------------------------
__global__ void __launch_bounds__(1024)
sort_kernel(const float* __restrict__ x1, const float* __restrict__ x2) {
    __shared__ float sk[NP];
    __shared__ short si[NP];

    const int s = blockIdx.x;
    const int w = s >> 5, b = s & 31;
    const float* src = (w ? x2 : x1) + (size_t)b * NP * 3;
    const int tid = threadIdx.x;

    for (int i = tid; i < NP; i += 1024) {
        sk[i] = src[3 * i];
        si[i] = (short)i;
    }
    __syncthreads();

    for (int k = 2; k <= NP; k <<= 1) {
        for (int j = k >> 1; j > 0; j >>= 1) {
            for (int i = tid; i < NP; i += 1024) {
                int ij = i ^ j;
                if (ij > i) {
                    bool up = ((i & k) == 0);
                    float a = sk[i], c = sk[ij];
                    bool sw = up ? (a > c) : (a < c);
                    if (sw) {
                        sk[i] = c; sk[ij] = a;
                        short t = si[i]; si[i] = si[ij]; si[ij] = t;
                    }
                }
            }
            __syncthreads();
        }
    }

    for (int i = tid; i < NP; i += 1024) {
        int idx = si[i];
        float x = src[3 * idx], y = src[3 * idx + 1], z = src[3 * idx + 2];
        g_pts[s][i] = make_float4(-2.0f * x, -2.0f * y, -2.0f * z,
                                  x * x + y * y + z * z);
        g_qid[s][i] = (unsigned short)idx;
    }
}

// ---------------------------------------------------------------------------
// 2) query: rank-window candidates in SMEM; outward scan with exact dx^2 stop.
//    grid = (NCHUNK, NSLOT), 256 threads, 2 queries/thread.
// ---------------------------------------------------------------------------
__global__ void __launch_bounds__(256)
query_kernel() {
    __shared__ float4 scand[WIN];

    const int ch = blockIdx.x;
    const int sq = blockIdx.y;
    const int sc = sq ^ 32;                      // opposite cloud, same batch
    const int tid = threadIdx.x;

    int c0 = QCH * ch - (WIN - QCH) / 2;         // center the window on the chunk
    c0 = min(max(c0, 0), NP - WIN);

    const float4* __restrict__ ptsc = g_pts[sc];
    const float4* __restrict__ ptsq = g_pts[sq];

    for (int j = tid; j < WIN; j += 256)
        scand[j] = ptsc[c0 + j];
    __syncthreads();

    #pragma unroll
    for (int u = 0; u < 2; u++) {
        const int qi = QCH * ch + u * 256 + tid;  // sorted query rank
        float4 qp = ptsq[qi];
        const int qid = g_qid[sq][qi];
        const float qx = -0.5f * qp.x;            // exact inverse of -2x
        const float qy = -0.5f * qp.y;
        const float qz = -0.5f * qp.z;
        const float qq = qp.w;
        const float qqe = qq + EPS;

        // lower_bound on x_c (= -0.5 * scand.x, ascending)
        int lo = 0, hi = WIN;
        while (lo < hi) {
            int mid = (lo + hi) >> 1;
            float xc = -0.5f * scand[mid].x;
            if (xc < qx) lo = mid + 1; else hi = mid;
        }
        const int pos = lo;

        float m = __int_as_float(0x7f800000);     // min of (cc - 2 q.c)

        // right scan (t = x_c - x_q, nondecreasing)
        int j = pos;
        for (; j < WIN; j++) {
            float4 c = scand[j];
            float t = fmaf(-0.5f, c.x, -qx);
            float u2 = fmaf(t, t, -m);            // t^2 - m
            if (u2 > qqe && t > 0.0f) break;
            m = fminf(m, fmaf(qx, c.x, fmaf(qy, c.y, fmaf(qz, c.z, c.w))));
        }
        if (j == WIN && c0 + WIN < NP) {          // rare spill right (global, sorted)
            for (int g = c0 + WIN; g < NP; g++) {
                float4 c = ptsc[g];
                float t = fmaf(-0.5f, c.x, -qx);
                float u2 = fmaf(t, t, -m);
                if (u2 > qqe && t > 0.0f) break;
                m = fminf(m, fmaf(qx, c.x, fmaf(qy, c.y, fmaf(qz, c.z, c.w))));
            }
        }

        // left scan (t nonincreasing, goes negative)
        j = pos - 1;
        for (; j >= 0; j--) {
            float4 c = scand[j];
            float t = fmaf(-0.5f, c.x, -qx);
            float u2 = fmaf(t, t, -m);
            if (u2 > qqe && t < 0.0f) break;
            m = fminf(m, fmaf(qx, c.x, fmaf(qy, c.y, fmaf(qz, c.z, c.w))));
        }
        if (j < 0 && c0 > 0) {                    // rare spill left
            for (int g = c0 - 1; g >= 0; g--) {
                float4 c = ptsc[g];
                float t = fmaf(-0.5f, c.x, -qx);
                float u2 = fmaf(t, t, -m);
                if (u2 > qqe && t < 0.0f) break;
                m = fminf(m, fmaf(qx, c.x, fmaf(qy, c.y, fmaf(qz, c.z, c.w))));
            }
        }

        g_dist[sq][qid] = qq + m;
    }
}

// ---------------------------------------------------------------------------
// 3) deterministic fixed-order reduce: out[b] = (sum_d0 + sum_d1) / NP
// ---------------------------------------------------------------------------
__global__ void __launch_bounds__(256)
reduce_kernel(float* __restrict__ out) {
    const int b = blockIdx.x, tid = threadIdx.x;
    float s = 0.0f;
    #pragma unroll
    for (int d = 0; d < 2; d++)
        for (int i = tid; i < NP; i += 256)
            s += g_dist[d * BATCH + b][i];

    __shared__ float red[256];
    red[tid] = s;
    __syncthreads();
    #pragma unroll
    for (int o = 128; o > 0; o >>= 1) {
        if (tid < o) red[tid] += red[tid + o];
        __syncthreads();
    }
    if (tid == 0) out[b] = red[0] * (1.0f / (float)NP);
}

extern "C" void kernel_launch(void* const* d_in, const int* in_sizes, int n_in,
                              void* d_out, int out_size) {
    const float* x1 = (const float*)d_in[0];
    const float* x2 = (const float*)d_in[1];
    float* out = (float*)d_out;

    sort_kernel<<<NSLOT, 1024>>>(x1, x2);
    query_kernel<<<dim3(NCHUNK, NSLOT), 256>>>();
    reduce_kernel<<<BATCH, 256>>>(out);
}

// round 10
// speedup vs baseline: 2.5279x; 2.1520x over previous
#include <cuda_runtime.h>

#define BATCH  32
#define NP     4096
#define NSLOT  64               // slot = w*32 + b; opposite cloud = s ^ 32
#define NB     128              // x-bins
#define XMIN   (-5.0f)
#define WB     0.078125f        // 10/128, exact in fp32
#define INVW   12.8f

// candidates binned by x, preprocessed: (-2x, -2y, -2z, ||c||^2)
__device__ float4         g_pts[NSLOT][NP];
__device__ unsigned short g_qid[NSLOT][NP];
__device__ int            g_binstart[NSLOT][NB + 1];
__device__ float          g_dist[NSLOT][NP];   // by ORIGINAL index

static __device__ __forceinline__ int bin_of(float x) {
    int b = (int)floorf((x - XMIN) * INVW);
    return min(max(b, 0), NB - 1);
}

// ---------------------------------------------------------------------------
// 1) per-slot counting sort by x-bin (+ preprocess).  One block per slot.
// ---------------------------------------------------------------------------
__global__ void __launch_bounds__(256)
prep_kernel(const float* __restrict__ x1, const float* __restrict__ x2) {
    __shared__ int hist[NB];
    __shared__ int bstart[NB + 1];
    __shared__ int cur[NB];

    const int s = blockIdx.x;
    const int w = s >> 5, b = s & 31;
    const float* src = (w ? x2 : x1) + (size_t)b * NP * 3;
    const int tid = threadIdx.x;

    if (tid < NB) hist[tid] = 0;
    __syncthreads();

    for (int i = tid; i < NP; i += 256)
        atomicAdd(&hist[bin_of(src[3 * i])], 1);
    __syncthreads();

    if (tid == 0) {
        int a = 0;
        for (int i = 0; i < NB; i++) { bstart[i] = a; a += hist[i]; }
        bstart[NB] = a;
    }
    __syncthreads();
    if (tid < NB) cur[tid] = bstart[tid];
    if (tid < NB + 1) g_binstart[s][tid] = bstart[tid];
    __syncthreads();

    for (int i = tid; i < NP; i += 256) {
        float x = src[3 * i], y = src[3 * i + 1], z = src[3 * i + 2];
        int bn = bin_of(x);
        int pos = atomicAdd(&cur[bn], 1);
        g_pts[s][pos] = make_float4(-2.0f * x, -2.0f * y, -2.0f * z,
                                    x * x + y * y + z * z);
        g_qid[s][pos] = (unsigned short)i;
    }
}

// ---------------------------------------------------------------------------
// 2) query: warp-uniform expanding bin-range scan, broadcast candidate loads.
//    grid = (NP/256, NSLOT), 256 threads, 1 query/thread (binned order).
// ---------------------------------------------------------------------------
#define SCAN_RANGE(S, E)                                                      \
    {                                                                         \
        int _i = (S);                                                         \
        for (; _i + 4 <= (E); _i += 4) {                                      \
            float4 c0 = ptsc[_i], c1 = ptsc[_i + 1];                          \
            float4 c2 = ptsc[_i + 2], c3 = ptsc[_i + 3];                      \
            m = fminf(m, fmaf(qx, c0.x, fmaf(qy, c0.y, fmaf(qz, c0.z, c0.w)))); \
            m = fminf(m, fmaf(qx, c1.x, fmaf(qy, c1.y, fmaf(qz, c1.z, c1.w)))); \
            m = fminf(m, fmaf(qx, c2.x, fmaf(qy, c2.y, fmaf(qz, c2.z, c2.w)))); \
            m = fminf(m, fmaf(qx, c3.x, fmaf(qy, c3.y, fmaf(qz, c3.z, c3.w)))); \
        }                                                                     \
        for (; _i < (E); _i++) {                                              \
            float4 c0 = ptsc[_i];                                             \
            m = fminf(m, fmaf(qx, c0.x, fmaf(qy, c0.y, fmaf(qz, c0.z, c0.w)))); \
        }                                                                     \
    }

__global__ void __launch_bounds__(256)
query_kernel() {
    const unsigned FULL = 0xffffffffu;
    const int sq = blockIdx.y;
    const int sc = sq ^ 32;                    // opposite cloud, same batch
    const int qi = blockIdx.x * 256 + threadIdx.x;

    const float4* __restrict__ ptsq = g_pts[sq];
    const float4* __restrict__ ptsc = g_pts[sc];
    const int*    __restrict__ bs   = g_binstart[sc];

    float4 qp = ptsq[qi];
    const int qid = g_qid[sq][qi];
    const float qx = -0.5f * qp.x;             // exact inverse of -2x
    const float qy = -0.5f * qp.y;
    const float qz = -0.5f * qp.z;
    const float qq = qp.w;

    const int qb = bin_of(qx);
    int lo = __reduce_min_sync(FULL, qb);      // warp-uniform range
    int hi = __reduce_max_sync(FULL, qb);
    lo = max(lo - 2, 0);
    hi = min(hi + 2, NB - 1);

    float m = __int_as_float(0x7f800000);      // min of (cc - 2 q.c)

    SCAN_RANGE(bs[lo], bs[hi + 1]);

    const float INF = __int_as_float(0x7f800000);
    while (true) {
        float bl = (lo == 0)      ? INF : qx - (XMIN + (float)lo * WB);
        float bh = (hi == NB - 1) ? INF : (XMIN + (float)(hi + 1) * WB) - qx;
        float bb = fminf(bl, bh);
        bool done = (qq + m) <= bb * bb * 0.9999f;
        if (__all_sync(FULL, done)) break;
        if (lo == 0 && hi == NB - 1) break;
        int nlo = max(lo - 1, 0);
        int nhi = min(hi + 1, NB - 1);
        if (nlo < lo) SCAN_RANGE(bs[nlo], bs[lo]);
        if (nhi > hi) SCAN_RANGE(bs[hi + 1], bs[nhi + 1]);
        lo = nlo; hi = nhi;
    }

    g_dist[sq][qid] = qq + m;
}

// ---------------------------------------------------------------------------
// 3) deterministic fixed-order reduce: out[b] = (sum_d0 + sum_d1) / NP
// ---------------------------------------------------------------------------
__global__ void __launch_bounds__(256)
reduce_kernel(float* __restrict__ out) {
    const int b = blockIdx.x, tid = threadIdx.x;
    float s = 0.0f;
    #pragma unroll
    for (int d = 0; d < 2; d++)
        for (int i = tid; i < NP; i += 256)
            s += g_dist[d * BATCH + b][i];

    __shared__ float red[256];
    red[tid] = s;
    __syncthreads();
    #pragma unroll
    for (int o = 128; o > 0; o >>= 1) {
        if (tid < o) red[tid] += red[tid + o];
        __syncthreads();
    }
    if (tid == 0) out[b] = red[0] * (1.0f / (float)NP);
}

extern "C" void kernel_launch(void* const* d_in, const int* in_sizes, int n_in,
                              void* d_out, int out_size) {
    const float* x1 = (const float*)d_in[0];
    const float* x2 = (const float*)d_in[1];
    float* out = (float*)d_out;

    prep_kernel<<<NSLOT, 256>>>(x1, x2);
    query_kernel<<<dim3(NP / 256, NSLOT), 256>>>();
    reduce_kernel<<<BATCH, 256>>>(out);
}